// round 1
// baseline (speedup 1.0000x reference)
#include <cuda_runtime.h>

#define B_MAX 8192
#define LODD 64
#define LSDD 128
#define ORGD 128
#define KMIX 16

// Scratch (static device globals; no allocation at runtime)
__device__ float g_c[B_MAX * LODD];      // c = x @ W_covar.T + b_covar
__device__ float g_obs[B_MAX * LODD];    // obs_mean
__device__ float g_tband[4 * 6 * KMIX * LODD]; // banded basis [mat][d][k][i]
__device__ float g_part[2048];           // per-block |c| partial sums
__device__ float g_inv;                  // 1 / sum(|c|)

__device__ __forceinline__ float eluf(float x) {
    return x > 0.f ? x : expm1f(x);
}

// ---------------------------------------------------------------------------
// k_extract: pull the 6 band diagonals out of tm11/tm12/tm21/tm22
// layout: g_tband[((mat*6 + d)*KMIX + k)*LODD + i], zero outside [0,64)
// ---------------------------------------------------------------------------
__global__ void k_extract(const float* __restrict__ t11, const float* __restrict__ t12,
                          const float* __restrict__ t21, const float* __restrict__ t22) {
    int idx = blockIdx.x * blockDim.x + threadIdx.x;
    const int total = 4 * 6 * KMIX * LODD;
    if (idx >= total) return;
    int i   = idx & 63;
    int k   = (idx >> 6) & 15;
    int rem = idx >> 10;           // mat*6 + d
    int d   = rem % 6;
    int mat = rem / 6;
    int j = i + d - 3;             // band offsets -3..2 (mask: -BW <= j-i <= BW-1)
    const float* src = (mat == 0) ? t11 : (mat == 1) ? t12 : (mat == 2) ? t21 : t22;
    float v = (j >= 0 && j < LODD) ? src[k * LODD * LODD + i * LODD + j] : 0.f;
    g_tband[idx] = v;
}

// ---------------------------------------------------------------------------
// k1: per-row h = x@Wm.T+bm ; c = x@Wc.T+bc ; obs = elu(h@Wn.T+bn)+1
//     writes g_c, g_obs; per-block partial sum of |c| -> g_part
// 256 threads = 64 outputs (i) x 4 column-groups (g); weights in registers.
// 64 rows per block, processed 4 at a time.
// ---------------------------------------------------------------------------
__global__ __launch_bounds__(256, 1)
void k1(const float* __restrict__ input,
        const float* __restrict__ Wm, const float* __restrict__ bm,
        const float* __restrict__ Wc, const float* __restrict__ bc,
        const float* __restrict__ Wn, const float* __restrict__ bn, int B) {
    __shared__ float x_sh[4][ORGD];
    __shared__ float pm[4][4][LODD];
    __shared__ float pc[4][4][LODD];
    __shared__ float pn[4][4][LODD];
    __shared__ float h_sh[4][LODD];
    __shared__ float red[256];

    int tid = threadIdx.x;
    int i = tid & 63;
    int g = tid >> 6;

    // Load per-thread weight slices into registers (one-time).
    float wm[32], wc[32], wn[16];
    {
        const float4* p = reinterpret_cast<const float4*>(Wm + i * ORGD + g * 32);
        #pragma unroll
        for (int v = 0; v < 8; v++) {
            float4 t = p[v];
            wm[4*v+0] = t.x; wm[4*v+1] = t.y; wm[4*v+2] = t.z; wm[4*v+3] = t.w;
        }
    }
    {
        const float4* p = reinterpret_cast<const float4*>(Wc + i * ORGD + g * 32);
        #pragma unroll
        for (int v = 0; v < 8; v++) {
            float4 t = p[v];
            wc[4*v+0] = t.x; wc[4*v+1] = t.y; wc[4*v+2] = t.z; wc[4*v+3] = t.w;
        }
    }
    {
        const float4* p = reinterpret_cast<const float4*>(Wn + i * LODD + g * 16);
        #pragma unroll
        for (int v = 0; v < 4; v++) {
            float4 t = p[v];
            wn[4*v+0] = t.x; wn[4*v+1] = t.y; wn[4*v+2] = t.z; wn[4*v+3] = t.w;
        }
    }

    float lsum = 0.f;
    int row_base = blockIdx.x * 64;

    for (int it = 0; it < 16; it++) {
        int r0 = row_base + it * 4;
        // load 4 input rows
        #pragma unroll
        for (int p = 0; p < 2; p++) {
            int idx = tid + p * 256;
            int rr = idx >> 7, ccol = idx & 127;
            int row = r0 + rr;
            x_sh[rr][ccol] = (row < B) ? input[row * ORGD + ccol] : 0.f;
        }
        __syncthreads();

        // partial dots for h and c
        #pragma unroll
        for (int rr = 0; rr < 4; rr++) {
            float am = 0.f, ac = 0.f;
            const float* xp = &x_sh[rr][g * 32];
            #pragma unroll
            for (int c = 0; c < 32; c += 4) {
                float4 xv = *reinterpret_cast<const float4*>(xp + c);
                am = fmaf(wm[c+0], xv.x, am); am = fmaf(wm[c+1], xv.y, am);
                am = fmaf(wm[c+2], xv.z, am); am = fmaf(wm[c+3], xv.w, am);
                ac = fmaf(wc[c+0], xv.x, ac); ac = fmaf(wc[c+1], xv.y, ac);
                ac = fmaf(wc[c+2], xv.z, ac); ac = fmaf(wc[c+3], xv.w, ac);
            }
            pm[rr][g][i] = am;
            pc[rr][g][i] = ac;
        }
        __syncthreads();

        // reduce h,c : thread -> (rr, ii)
        {
            int rr = tid >> 6, ii = tid & 63;
            float h = bm[ii] + pm[rr][0][ii] + pm[rr][1][ii] + pm[rr][2][ii] + pm[rr][3][ii];
            float cv = bc[ii] + pc[rr][0][ii] + pc[rr][1][ii] + pc[rr][2][ii] + pc[rr][3][ii];
            h_sh[rr][ii] = h;
            int row = r0 + rr;
            if (row < B) {
                g_c[row * LODD + ii] = cv;
                lsum += fabsf(cv);
            }
        }
        __syncthreads();

        // norm partials
        #pragma unroll
        for (int rr = 0; rr < 4; rr++) {
            float an = 0.f;
            const float* hp = &h_sh[rr][g * 16];
            #pragma unroll
            for (int c = 0; c < 16; c++) an = fmaf(wn[c], hp[c], an);
            pn[rr][g][i] = an;
        }
        __syncthreads();

        // norm reduce + elu + store obs_mean
        {
            int rr = tid >> 6, ii = tid & 63;
            float o = bn[ii] + pn[rr][0][ii] + pn[rr][1][ii] + pn[rr][2][ii] + pn[rr][3][ii];
            int row = r0 + rr;
            if (row < B) g_obs[row * LODD + ii] = eluf(o) + 1.f;
        }
        __syncthreads();
    }

    // deterministic block reduce of |c|
    red[tid] = lsum;
    __syncthreads();
    #pragma unroll
    for (int s = 128; s > 0; s >>= 1) {
        if (tid < s) red[tid] += red[tid + s];
        __syncthreads();
    }
    if (tid == 0) g_part[blockIdx.x] = red[0];
}

// ---------------------------------------------------------------------------
// k_sum: deterministic reduce of per-block partials -> g_inv
// ---------------------------------------------------------------------------
__global__ void k_sum(int nb) {
    __shared__ float red[256];
    int tid = threadIdx.x;
    float s = 0.f;
    for (int idx = tid; idx < nb; idx += 256) s += g_part[idx];
    red[tid] = s;
    __syncthreads();
    #pragma unroll
    for (int st = 128; st > 0; st >>= 1) {
        if (tid < st) red[tid] += red[tid + st];
        __syncthreads();
    }
    if (tid == 0) g_inv = 1.f / red[0];
}

// ---------------------------------------------------------------------------
// k2: coeff softmax, band blend, banded quadratic forms, Kalman update.
// 256 threads = 64 i x 4 mat. Each thread keeps its 96 basis values in regs.
// 64 rows per block.
// ---------------------------------------------------------------------------
__global__ __launch_bounds__(256, 1)
void k2(const float* __restrict__ state,
        const float* __restrict__ Wk, const float* __restrict__ bk,
        const float* __restrict__ ltc, float* __restrict__ out, int B) {
    __shared__ float post_sh[4][LSDD];
    __shared__ float partc[4][16][16];       // [rr][seg][klog]
    __shared__ float coeff_sh[64][KMIX];
    __shared__ float blend_sh[2][4 * 6 * LODD];
    __shared__ float st_sh[2][320];
    __shared__ float tc_sh[LSDD];

    int tid = threadIdx.x;
    int row_base = blockIdx.x * 64;

    if (tid < LSDD) tc_sh[tid] = eluf(ltc[tid]) + 1.f;

    // basis registers: thread (i, mat) owns 6 diags x 16 k
    int i = tid & 63;
    int mat = tid >> 6;
    float treg[96];
    {
        const float* tb = g_tband + mat * 6 * KMIX * LODD + i;
        #pragma unroll
        for (int dk = 0; dk < 96; dk++) treg[dk] = tb[dk * LODD];
    }

    // coeff weight slice: thread (klog, seg) owns 8 cols of W_coef[klog]
    int klog = tid & 15;
    int seg = tid >> 4;
    float wcf[8];
    {
        const float4* p = reinterpret_cast<const float4*>(Wk + klog * LSDD + seg * 8);
        float4 a = p[0], b = p[1];
        wcf[0]=a.x; wcf[1]=a.y; wcf[2]=a.z; wcf[3]=a.w;
        wcf[4]=b.x; wcf[5]=b.y; wcf[6]=b.z; wcf[7]=b.w;
    }

    // Phase 1: logits for all 64 rows
    for (int it = 0; it < 16; it++) {
        int r0 = row_base + it * 4;
        #pragma unroll
        for (int p = 0; p < 2; p++) {
            int idx = tid + p * 256;
            int rr = idx >> 7, c = idx & 127;
            int row = r0 + rr;
            post_sh[rr][c] = (row < B) ? state[row * 320 + c] : 0.f;
        }
        __syncthreads();
        #pragma unroll
        for (int rr = 0; rr < 4; rr++) {
            const float* pp = &post_sh[rr][seg * 8];
            float a = 0.f;
            #pragma unroll
            for (int j = 0; j < 8; j++) a = fmaf(wcf[j], pp[j], a);
            partc[rr][seg][klog] = a;
        }
        __syncthreads();
        if (tid < 64) {
            int rr = tid >> 4, k = tid & 15;
            float l = bk[k];
            #pragma unroll
            for (int s = 0; s < 16; s++) l += partc[rr][s][k];
            coeff_sh[it * 4 + rr][k] = l;
        }
        __syncthreads();
    }

    // softmax per row (one thread per row)
    if (tid < 64) {
        float mx = -1e30f;
        #pragma unroll
        for (int k = 0; k < 16; k++) mx = fmaxf(mx, coeff_sh[tid][k]);
        float e[16];
        float s = 0.f;
        #pragma unroll
        for (int k = 0; k < 16; k++) { e[k] = expf(coeff_sh[tid][k] - mx); s += e[k]; }
        float inv = 1.f / s;
        #pragma unroll
        for (int k = 0; k < 16; k++) coeff_sh[tid][k] = e[k] * inv;
    }
    __syncthreads();

    float inv_sum = g_inv;

    // Phase 3: per-row blend + banded ops (double-buffered, 1 sync/row)
    for (int r = 0; r < 64; r++) {
        int buf = r & 1;
        int row = row_base + r;
        for (int c = tid; c < 320; c += 256)
            st_sh[buf][c] = (row < B) ? state[row * 320 + c] : 0.f;

        // blend: acc[d] = sum_k coeff[r][k] * basis[mat][d][k][i]
        float acc[6] = {0.f, 0.f, 0.f, 0.f, 0.f, 0.f};
        #pragma unroll
        for (int k = 0; k < KMIX; k++) {
            float cf = coeff_sh[r][k];
            #pragma unroll
            for (int d = 0; d < 6; d++) acc[d] = fmaf(cf, treg[d * 16 + k], acc[d]);
        }
        {
            float* bl = &blend_sh[buf][mat * 6 * LODD];
            #pragma unroll
            for (int d = 0; d < 6; d++) bl[d * LODD + i] = acc[d];
        }
        __syncthreads();

        if (tid < 64) {
            const float* blb = blend_sh[buf];
            float b11[6], b12[6], b21[6], b22[6];
            #pragma unroll
            for (int d = 0; d < 6; d++) {
                b11[d] = blb[0 * 384 + d * 64 + tid];
                b12[d] = blb[1 * 384 + d * 64 + tid];
                b21[d] = blb[2 * 384 + d * 64 + tid];
                b22[d] = blb[3 * 384 + d * 64 + tid];
            }
            const float* st = st_sh[buf];
            float pmu = 0.f, pml = 0.f, pcu = 0.f, pcl = 0.f, pcs = 0.f;
            #pragma unroll
            for (int d = 0; d < 6; d++) {
                int j = tid + d - 3;
                int jc = min(max(j, 0), 63);   // basis is 0 outside band, read safely
                float pu  = st[jc];
                float pl2 = st[64 + jc];
                float cuj = st[128 + jc];
                float clj = st[192 + jc];
                float csj = st[256 + jc];
                pmu = fmaf(b11[d], pu, pmu); pmu = fmaf(b12[d], pl2, pmu);
                pml = fmaf(b21[d], pu, pml); pml = fmaf(b22[d], pl2, pml);
                pcu = fmaf(b11[d] * b11[d], cuj, pcu);
                pcu = fmaf(2.f * b11[d] * b12[d], csj, pcu);
                pcu = fmaf(b12[d] * b12[d], clj, pcu);
                pcl = fmaf(b21[d] * b21[d], cuj, pcl);
                pcl = fmaf(2.f * b21[d] * b22[d], csj, pcl);
                pcl = fmaf(b22[d] * b22[d], clj, pcl);
                pcs = fmaf(b21[d] * b11[d], cuj, pcs);
                pcs = fmaf(b22[d] * b11[d] + b21[d] * b12[d], csj, pcs);
                pcs = fmaf(b22[d] * b12[d], clj, pcs);
            }
            pcu += tc_sh[tid];
            pcl += tc_sh[64 + tid];

            if (row < B) {
                float cv = g_c[row * 64 + tid];
                float om = g_obs[row * 64 + tid];
                float ocov = cv * inv_sum;
                float denom = pcu + ocov;
                float qu = pcu / denom;
                float ql = pcs / denom;
                float res = om - pmu;
                float* o = out + row * 320;
                o[tid]        = pmu + qu * res;
                o[64 + tid]   = pml + ql * res;
                o[128 + tid]  = (1.f - qu) * pcu;
                o[192 + tid]  = pcl - ql * pcs;
                o[256 + tid]  = (1.f - qu) * pcs;
            }
        }
    }
}

// ---------------------------------------------------------------------------
extern "C" void kernel_launch(void* const* d_in, const int* in_sizes, int n_in,
                              void* d_out, int out_size) {
    const float* input  = (const float*)d_in[0];
    const float* state  = (const float*)d_in[1];
    const float* W_mean = (const float*)d_in[2];
    const float* b_mean = (const float*)d_in[3];
    const float* W_cov  = (const float*)d_in[4];
    const float* b_cov  = (const float*)d_in[5];
    const float* W_norm = (const float*)d_in[6];
    const float* b_norm = (const float*)d_in[7];
    const float* W_coef = (const float*)d_in[8];
    const float* b_coef = (const float*)d_in[9];
    const float* tm11   = (const float*)d_in[10];
    const float* tm12   = (const float*)d_in[11];
    const float* tm21   = (const float*)d_in[12];
    const float* tm22   = (const float*)d_in[13];
    const float* ltc    = (const float*)d_in[14];
    float* out = (float*)d_out;

    int B = in_sizes[0] / ORGD;
    int nb = (B + 63) / 64;

    const int extract_total = 4 * 6 * KMIX * LODD;
    k_extract<<<(extract_total + 255) / 256, 256>>>(tm11, tm12, tm21, tm22);
    k1<<<nb, 256>>>(input, W_mean, b_mean, W_cov, b_cov, W_norm, b_norm, B);
    k_sum<<<1, 256>>>(nb);
    k2<<<nb, 256>>>(state, W_coef, b_coef, ltc, out, B);
}

// round 3
// speedup vs baseline: 1.3060x; 1.3060x over previous
#include <cuda_runtime.h>

#define B_MAX 8192
#define LODD 64
#define LSDD 128
#define ORGD 128
#define KMIX 16
#define RPB 56            // rows per block -> grid 147 on 148 SMs

typedef unsigned long long ull;

// Scratch (static device globals; no allocation at runtime)
__device__ float g_c[B_MAX * LODD];          // c = x @ W_covar.T + b_covar
__device__ float g_obs[B_MAX * LODD];        // obs_mean
__device__ ull   g_tband2[4 * KMIX * 3 * LODD]; // paired band basis [mat][k][pair][i], pair=(d,d+1)
__device__ float g_part[2048];               // per-block |c| partial sums
__device__ float g_inv;                      // 1 / sum(|c|)

__device__ __forceinline__ float eluf(float x) {
    return x > 0.f ? x : expm1f(x);
}

__device__ __forceinline__ ull pack2(float lo, float hi) {
    ull d;
    asm("mov.b64 %0, {%1, %2};" : "=l"(d) : "r"(__float_as_uint(lo)), "r"(__float_as_uint(hi)));
    return d;
}
__device__ __forceinline__ void unpack2(float& lo, float& hi, ull v) {
    unsigned int a, b;
    asm("mov.b64 {%0, %1}, %2;" : "=r"(a), "=r"(b) : "l"(v));
    lo = __uint_as_float(a); hi = __uint_as_float(b);
}
__device__ __forceinline__ void fma2(ull& d, ull a, ull b) {
    asm("fma.rn.f32x2 %0, %1, %2, %0;" : "+l"(d) : "l"(a), "l"(b));
}

// ---------------------------------------------------------------------------
// k_extract: pull the 6 band diagonals (offsets -3..2) out of tm11..tm22,
// paired layout: g_tband2[((mat*16 + k)*3 + p)*64 + i] = (t[d=2p], t[d=2p+1])
// zero outside [0,64).
// ---------------------------------------------------------------------------
__global__ void k_extract(const float* __restrict__ t11, const float* __restrict__ t12,
                          const float* __restrict__ t21, const float* __restrict__ t22) {
    int idx = blockIdx.x * blockDim.x + threadIdx.x;
    const int total = 4 * KMIX * 3 * LODD;
    if (idx >= total) return;
    int i = idx & 63;
    int p = (idx >> 6) % 3;
    int k = (idx / (3 * 64)) & 15;
    int mat = idx / (16 * 3 * 64);
    const float* src = (mat == 0) ? t11 : (mat == 1) ? t12 : (mat == 2) ? t21 : t22;
    int d0 = 2 * p, d1 = 2 * p + 1;
    int j0 = i + d0 - 3, j1 = i + d1 - 3;
    float v0 = (j0 >= 0 && j0 < LODD) ? src[k * LODD * LODD + i * LODD + j0] : 0.f;
    float v1 = (j1 >= 0 && j1 < LODD) ? src[k * LODD * LODD + i * LODD + j1] : 0.f;
    g_tband2[idx] = pack2(v0, v1);
}

// ---------------------------------------------------------------------------
// k1: per-row h = x@Wm.T+bm ; c = x@Wc.T+bc ; obs = elu(h@Wn.T+bn)+1
// 256 threads = 64 outputs (i) x 4 column-groups (g); weights in registers.
// f32x2 paired accumulation along the column axis.
// ---------------------------------------------------------------------------
__global__ __launch_bounds__(256, 1)
void k1(const float* __restrict__ input,
        const float* __restrict__ Wm, const float* __restrict__ bm,
        const float* __restrict__ Wc, const float* __restrict__ bc,
        const float* __restrict__ Wn, const float* __restrict__ bn, int B) {
    __shared__ float x_sh[4][ORGD];
    __shared__ float pm[4][4][LODD];
    __shared__ float pc[4][4][LODD];
    __shared__ float pn[4][4][LODD];
    __shared__ float h_sh[4][LODD];
    __shared__ float red[256];

    int tid = threadIdx.x;
    int i = tid & 63;
    int g = tid >> 6;

    // weight slices in registers, paired along columns
    ull wm2[16], wc2[16], wn2[8];
    {
        const ull* p = reinterpret_cast<const ull*>(Wm + i * ORGD + g * 32);
        #pragma unroll
        for (int v = 0; v < 16; v++) wm2[v] = p[v];
    }
    {
        const ull* p = reinterpret_cast<const ull*>(Wc + i * ORGD + g * 32);
        #pragma unroll
        for (int v = 0; v < 16; v++) wc2[v] = p[v];
    }
    {
        const ull* p = reinterpret_cast<const ull*>(Wn + i * LODD + g * 16);
        #pragma unroll
        for (int v = 0; v < 8; v++) wn2[v] = p[v];
    }

    float lsum = 0.f;
    int row_base = blockIdx.x * RPB;
    const int iters = RPB / 4;

    for (int it = 0; it < iters; it++) {
        int r0 = row_base + it * 4;
        // load 4 input rows
        #pragma unroll
        for (int p = 0; p < 2; p++) {
            int idx = tid + p * 256;
            int rr = idx >> 7, ccol = idx & 127;
            int row = r0 + rr;
            x_sh[rr][ccol] = (row < B) ? input[row * ORGD + ccol] : 0.f;
        }
        __syncthreads();

        // partial dots for h and c (f32x2)
        #pragma unroll
        for (int rr = 0; rr < 4; rr++) {
            ull am2 = 0, ac2 = 0;
            const float* xp = &x_sh[rr][g * 32];
            #pragma unroll
            for (int c2 = 0; c2 < 16; c2++) {
                ull xv = *reinterpret_cast<const ull*>(xp + 2 * c2);
                fma2(am2, wm2[c2], xv);
                fma2(ac2, wc2[c2], xv);
            }
            float a0, a1, b0, b1;
            unpack2(a0, a1, am2);
            unpack2(b0, b1, ac2);
            pm[rr][g][i] = a0 + a1;
            pc[rr][g][i] = b0 + b1;
        }
        __syncthreads();

        // reduce h,c
        {
            int rr = tid >> 6, ii = tid & 63;
            float h = bm[ii] + pm[rr][0][ii] + pm[rr][1][ii] + pm[rr][2][ii] + pm[rr][3][ii];
            float cv = bc[ii] + pc[rr][0][ii] + pc[rr][1][ii] + pc[rr][2][ii] + pc[rr][3][ii];
            h_sh[rr][ii] = h;
            int row = r0 + rr;
            if (row < B) {
                g_c[row * LODD + ii] = cv;
                lsum += fabsf(cv);
            }
        }
        __syncthreads();

        // norm partials (f32x2)
        #pragma unroll
        for (int rr = 0; rr < 4; rr++) {
            ull an2 = 0;
            const float* hp = &h_sh[rr][g * 16];
            #pragma unroll
            for (int c2 = 0; c2 < 8; c2++) {
                ull hv = *reinterpret_cast<const ull*>(hp + 2 * c2);
                fma2(an2, wn2[c2], hv);
            }
            float n0, n1;
            unpack2(n0, n1, an2);
            pn[rr][g][i] = n0 + n1;
        }
        __syncthreads();

        // norm reduce + elu + store obs_mean
        {
            int rr = tid >> 6, ii = tid & 63;
            float o = bn[ii] + pn[rr][0][ii] + pn[rr][1][ii] + pn[rr][2][ii] + pn[rr][3][ii];
            int row = r0 + rr;
            if (row < B) g_obs[row * LODD + ii] = eluf(o) + 1.f;
        }
        __syncthreads();
    }

    // deterministic block reduce of |c|
    red[tid] = lsum;
    __syncthreads();
    #pragma unroll
    for (int s = 128; s > 0; s >>= 1) {
        if (tid < s) red[tid] += red[tid + s];
        __syncthreads();
    }
    if (tid == 0) g_part[blockIdx.x] = red[0];
}

// ---------------------------------------------------------------------------
// k_sum: deterministic reduce of per-block partials -> g_inv
// ---------------------------------------------------------------------------
__global__ void k_sum(int nb) {
    __shared__ float red[256];
    int tid = threadIdx.x;
    float s = 0.f;
    for (int idx = tid; idx < nb; idx += 256) s += g_part[idx];
    red[tid] = s;
    __syncthreads();
    #pragma unroll
    for (int st = 128; st > 0; st >>= 1) {
        if (tid < st) red[tid] += red[tid + st];
        __syncthreads();
    }
    if (tid == 0) g_inv = 1.f / red[0];
}

// ---------------------------------------------------------------------------
// k2: coeff softmax, band blend (f32x2), banded quadratic forms, update.
// 256 threads. Blend: (i, mat) threads, 4 rows per iteration.
// Banded: (rr, i) threads -> all 256 active. 2 syncs per 4 rows.
// ---------------------------------------------------------------------------
__global__ __launch_bounds__(256, 1)
void k2(const float* __restrict__ state,
        const float* __restrict__ Wk, const float* __restrict__ bk,
        const float* __restrict__ ltc, float* __restrict__ out, int B) {
    __shared__ float post_sh[4][LSDD];
    __shared__ float partc[4][16][16];       // [rr][seg][klog]
    __shared__ float coeff_sh[RPB][KMIX];
    __shared__ ull   blend2[4][4][3][LODD];  // [rr][mat][pair][i]
    __shared__ float st_sh[4][320];
    __shared__ float tc_sh[LSDD];

    int tid = threadIdx.x;
    int row_base = blockIdx.x * RPB;
    const int iters = RPB / 4;

    if (tid < LSDD) tc_sh[tid] = eluf(ltc[tid]) + 1.f;

    // basis registers: thread (i, mat) owns 3 diag-pairs x 16 k
    int i = tid & 63;
    int mat = tid >> 6;
    ull treg2[48];
    {
        const ull* tb = g_tband2 + (mat * KMIX * 3) * LODD + i;
        #pragma unroll
        for (int kp = 0; kp < 48; kp++) treg2[kp] = tb[kp * LODD];
    }

    // coeff weight slice: thread (klog, seg) owns 8 cols of W_coef[klog]
    int klog = tid & 15;
    int seg = tid >> 4;
    float wcf[8];
    {
        const float4* p = reinterpret_cast<const float4*>(Wk + klog * LSDD + seg * 8);
        float4 a = p[0], b = p[1];
        wcf[0]=a.x; wcf[1]=a.y; wcf[2]=a.z; wcf[3]=a.w;
        wcf[4]=b.x; wcf[5]=b.y; wcf[6]=b.z; wcf[7]=b.w;
    }

    // Phase 1: logits for all rows of this block
    for (int it = 0; it < iters; it++) {
        int r0 = row_base + it * 4;
        #pragma unroll
        for (int p = 0; p < 2; p++) {
            int idx = tid + p * 256;
            int rr = idx >> 7, c = idx & 127;
            int row = r0 + rr;
            post_sh[rr][c] = (row < B) ? state[row * 320 + c] : 0.f;
        }
        __syncthreads();
        #pragma unroll
        for (int rr = 0; rr < 4; rr++) {
            const float* pp = &post_sh[rr][seg * 8];
            float a = 0.f;
            #pragma unroll
            for (int j = 0; j < 8; j++) a = fmaf(wcf[j], pp[j], a);
            partc[rr][seg][klog] = a;
        }
        __syncthreads();
        if (tid < 64) {
            int rr = tid >> 4, k = tid & 15;
            float l = bk[k];
            #pragma unroll
            for (int s = 0; s < 16; s++) l += partc[rr][s][k];
            coeff_sh[it * 4 + rr][k] = l;
        }
        __syncthreads();
    }

    // softmax per row
    if (tid < RPB) {
        float mx = -1e30f;
        #pragma unroll
        for (int k = 0; k < 16; k++) mx = fmaxf(mx, coeff_sh[tid][k]);
        float e[16];
        float s = 0.f;
        #pragma unroll
        for (int k = 0; k < 16; k++) { e[k] = __expf(coeff_sh[tid][k] - mx); s += e[k]; }
        float inv = 1.f / s;
        #pragma unroll
        for (int k = 0; k < 16; k++) coeff_sh[tid][k] = e[k] * inv;
    }
    float inv_sum = g_inv;
    __syncthreads();

    // Phase 3: 4 rows per iteration
    for (int it = 0; it < iters; it++) {
        int r0 = row_base + it * 4;

        // load 4 state rows
        for (int idx = tid; idx < 4 * 320; idx += 256) {
            int rr = idx / 320, cc = idx - rr * 320;
            int row = r0 + rr;
            st_sh[rr][cc] = (row < B) ? state[row * 320 + cc] : 0.f;
        }

        // blend 4 rows: thread (i, mat), f32x2 over diag pairs
        #pragma unroll
        for (int rr = 0; rr < 4; rr++) {
            int lr = it * 4 + rr;
            ull a0 = 0, a1 = 0, a2 = 0;
            #pragma unroll
            for (int k = 0; k < KMIX; k++) {
                float cf = coeff_sh[lr][k];
                ull cf2 = pack2(cf, cf);
                fma2(a0, cf2, treg2[k * 3 + 0]);
                fma2(a1, cf2, treg2[k * 3 + 1]);
                fma2(a2, cf2, treg2[k * 3 + 2]);
            }
            blend2[rr][mat][0][i] = a0;
            blend2[rr][mat][1][i] = a1;
            blend2[rr][mat][2][i] = a2;
        }
        __syncthreads();

        // banded phase: thread (rr, ii), all 256 active
        {
            int rr = tid >> 6, ii = tid & 63;
            int row = r0 + rr;

            float b11[6], b12[6], b21[6], b22[6];
            unpack2(b11[0], b11[1], blend2[rr][0][0][ii]);
            unpack2(b11[2], b11[3], blend2[rr][0][1][ii]);
            unpack2(b11[4], b11[5], blend2[rr][0][2][ii]);
            unpack2(b12[0], b12[1], blend2[rr][1][0][ii]);
            unpack2(b12[2], b12[3], blend2[rr][1][1][ii]);
            unpack2(b12[4], b12[5], blend2[rr][1][2][ii]);
            unpack2(b21[0], b21[1], blend2[rr][2][0][ii]);
            unpack2(b21[2], b21[3], blend2[rr][2][1][ii]);
            unpack2(b21[4], b21[5], blend2[rr][2][2][ii]);
            unpack2(b22[0], b22[1], blend2[rr][3][0][ii]);
            unpack2(b22[2], b22[3], blend2[rr][3][1][ii]);
            unpack2(b22[4], b22[5], blend2[rr][3][2][ii]);

            const float* st = st_sh[rr];
            float pmu = 0.f, pml = 0.f, pcu = 0.f, pcl = 0.f, pcs = 0.f;
            #pragma unroll
            for (int d = 0; d < 6; d++) {
                int j = ii + d - 3;
                int jc = min(max(j, 0), 63);   // basis is 0 outside band
                float pu  = st[jc];
                float pl2 = st[64 + jc];
                float cuj = st[128 + jc];
                float clj = st[192 + jc];
                float csj = st[256 + jc];
                pmu = fmaf(b11[d], pu, pmu); pmu = fmaf(b12[d], pl2, pmu);
                pml = fmaf(b21[d], pu, pml); pml = fmaf(b22[d], pl2, pml);
                pcu = fmaf(b11[d] * b11[d], cuj, pcu);
                pcu = fmaf(2.f * b11[d] * b12[d], csj, pcu);
                pcu = fmaf(b12[d] * b12[d], clj, pcu);
                pcl = fmaf(b21[d] * b21[d], cuj, pcl);
                pcl = fmaf(2.f * b21[d] * b22[d], csj, pcl);
                pcl = fmaf(b22[d] * b22[d], clj, pcl);
                pcs = fmaf(b21[d] * b11[d], cuj, pcs);
                pcs = fmaf(b22[d] * b11[d] + b21[d] * b12[d], csj, pcs);
                pcs = fmaf(b22[d] * b12[d], clj, pcs);
            }
            pcu += tc_sh[ii];
            pcl += tc_sh[64 + ii];

            if (row < B) {
                float cv = g_c[row * 64 + ii];
                float om = g_obs[row * 64 + ii];
                float ocov = cv * inv_sum;
                float denom = pcu + ocov;
                float qu = pcu / denom;
                float ql = pcs / denom;
                float res = om - pmu;
                float* o = out + row * 320;
                o[ii]        = pmu + qu * res;
                o[64 + ii]   = pml + ql * res;
                o[128 + ii]  = (1.f - qu) * pcu;
                o[192 + ii]  = pcl - ql * pcs;
                o[256 + ii]  = (1.f - qu) * pcs;
            }
        }
        __syncthreads();
    }
}

// ---------------------------------------------------------------------------
extern "C" void kernel_launch(void* const* d_in, const int* in_sizes, int n_in,
                              void* d_out, int out_size) {
    const float* input  = (const float*)d_in[0];
    const float* state  = (const float*)d_in[1];
    const float* W_mean = (const float*)d_in[2];
    const float* b_mean = (const float*)d_in[3];
    const float* W_cov  = (const float*)d_in[4];
    const float* b_cov  = (const float*)d_in[5];
    const float* W_norm = (const float*)d_in[6];
    const float* b_norm = (const float*)d_in[7];
    const float* W_coef = (const float*)d_in[8];
    const float* b_coef = (const float*)d_in[9];
    const float* tm11   = (const float*)d_in[10];
    const float* tm12   = (const float*)d_in[11];
    const float* tm21   = (const float*)d_in[12];
    const float* tm22   = (const float*)d_in[13];
    const float* ltc    = (const float*)d_in[14];
    float* out = (float*)d_out;

    int B = in_sizes[0] / ORGD;
    int nb = (B + RPB - 1) / RPB;

    const int extract_total = 4 * KMIX * 3 * LODD;
    k_extract<<<(extract_total + 255) / 256, 256>>>(tm11, tm12, tm21, tm22);
    k1<<<nb, 256>>>(input, W_mean, b_mean, W_cov, b_cov, W_norm, b_norm, B);
    k_sum<<<1, 256>>>(nb);
    k2<<<nb, 256>>>(state, W_coef, b_coef, ltc, out, B);
}

// round 11
// speedup vs baseline: 1.3771x; 1.0545x over previous
#include <cuda_runtime.h>

#define B_MAX 8192
#define LODD 64
#define ORGD 128
#define KMIX 16
#define RPB 56            // rows per row-block -> 147 row-blocks; x2 i-halves = 294 blocks

typedef unsigned long long ull;

// Scratch (static device globals; no allocation at runtime)
__device__ float g_c[B_MAX * LODD];          // c = x @ W_covar.T + b_covar
__device__ float g_obs[B_MAX * LODD];        // obs_mean
__device__ float g_tbandP[4 * 6 * LODD * 18]; // band basis [mat][d][i][k(pad 18)]
__device__ float g_part[2048];               // per-block |c| partial sums
__device__ float g_inv;                      // 1 / sum(|c|)

__device__ __forceinline__ float eluf(float x) {
    return x > 0.f ? x : expm1f(x);
}

__device__ __forceinline__ ull pack2(float lo, float hi) {
    ull d;
    asm("mov.b64 %0, {%1, %2};" : "=l"(d) : "r"(__float_as_uint(lo)), "r"(__float_as_uint(hi)));
    return d;
}
__device__ __forceinline__ void unpack2(float& lo, float& hi, ull v) {
    unsigned int a, b;
    asm("mov.b64 {%0, %1}, %2;" : "=r"(a), "=r"(b) : "l"(v));
    lo = __uint_as_float(a); hi = __uint_as_float(b);
}
__device__ __forceinline__ void fma2(ull& d, ull a, ull b) {
    asm("fma.rn.f32x2 %0, %1, %2, %0;" : "+l"(d) : "l"(a), "l"(b));
}

// ---------------------------------------------------------------------------
// k_extract: band diagonals (offsets d-3, d in 0..5) of tm11..tm22 into
// g_tbandP[((mat*6 + d)*64 + i)*18 + k], k padded 16->18 (8B-aligned i-rows).
// ---------------------------------------------------------------------------
__global__ void k_extract(const float* __restrict__ t11, const float* __restrict__ t12,
                          const float* __restrict__ t21, const float* __restrict__ t22) {
    int idx = blockIdx.x * blockDim.x + threadIdx.x;
    const int total = 4 * 6 * LODD * 18;
    if (idx >= total) return;
    int k = idx % 18;
    int i = (idx / 18) & 63;
    int d = (idx / (18 * 64)) % 6;
    int mat = idx / (18 * 64 * 6);
    float v = 0.f;
    if (k < KMIX) {
        int j = i + d - 3;
        if (j >= 0 && j < LODD) {
            const float* src = (mat == 0) ? t11 : (mat == 1) ? t12 : (mat == 2) ? t21 : t22;
            v = src[k * LODD * LODD + i * LODD + j];
        }
    }
    g_tbandP[idx] = v;
}

// ---------------------------------------------------------------------------
// k1: per-row h = x@Wm.T+bm ; c = x@Wc.T+bc ; obs = elu(h@Wn.T+bn)+1
// ---------------------------------------------------------------------------
__global__ __launch_bounds__(256, 1)
void k1(const float* __restrict__ input,
        const float* __restrict__ Wm, const float* __restrict__ bm,
        const float* __restrict__ Wc, const float* __restrict__ bc,
        const float* __restrict__ Wn, const float* __restrict__ bn, int B) {
    __shared__ float x_sh[4][ORGD];
    __shared__ float pm[4][4][LODD];
    __shared__ float pc[4][4][LODD];
    __shared__ float pn[4][4][LODD];
    __shared__ float h_sh[4][LODD];
    __shared__ float red[256];

    int tid = threadIdx.x;
    int i = tid & 63;
    int g = tid >> 6;

    ull wm2[16], wc2[16], wn2[8];
    {
        const ull* p = reinterpret_cast<const ull*>(Wm + i * ORGD + g * 32);
        #pragma unroll
        for (int v = 0; v < 16; v++) wm2[v] = p[v];
    }
    {
        const ull* p = reinterpret_cast<const ull*>(Wc + i * ORGD + g * 32);
        #pragma unroll
        for (int v = 0; v < 16; v++) wc2[v] = p[v];
    }
    {
        const ull* p = reinterpret_cast<const ull*>(Wn + i * LODD + g * 16);
        #pragma unroll
        for (int v = 0; v < 8; v++) wn2[v] = p[v];
    }

    float lsum = 0.f;
    int row_base = blockIdx.x * RPB;
    const int iters = RPB / 4;

    for (int it = 0; it < iters; it++) {
        int r0 = row_base + it * 4;
        #pragma unroll
        for (int p = 0; p < 2; p++) {
            int idx = tid + p * 256;
            int rr = idx >> 7, ccol = idx & 127;
            int row = r0 + rr;
            x_sh[rr][ccol] = (row < B) ? input[row * ORGD + ccol] : 0.f;
        }
        __syncthreads();

        #pragma unroll
        for (int rr = 0; rr < 4; rr++) {
            ull am2 = 0, ac2 = 0;
            const float* xp = &x_sh[rr][g * 32];
            #pragma unroll
            for (int c2 = 0; c2 < 16; c2++) {
                ull xv = *reinterpret_cast<const ull*>(xp + 2 * c2);
                fma2(am2, wm2[c2], xv);
                fma2(ac2, wc2[c2], xv);
            }
            float a0, a1, b0, b1;
            unpack2(a0, a1, am2);
            unpack2(b0, b1, ac2);
            pm[rr][g][i] = a0 + a1;
            pc[rr][g][i] = b0 + b1;
        }
        __syncthreads();

        {
            int rr = tid >> 6, ii = tid & 63;
            float h = bm[ii] + pm[rr][0][ii] + pm[rr][1][ii] + pm[rr][2][ii] + pm[rr][3][ii];
            float cv = bc[ii] + pc[rr][0][ii] + pc[rr][1][ii] + pc[rr][2][ii] + pc[rr][3][ii];
            h_sh[rr][ii] = h;
            int row = r0 + rr;
            if (row < B) {
                g_c[row * LODD + ii] = cv;
                lsum += fabsf(cv);
            }
        }
        __syncthreads();

        #pragma unroll
        for (int rr = 0; rr < 4; rr++) {
            ull an2 = 0;
            const float* hp = &h_sh[rr][g * 16];
            #pragma unroll
            for (int c2 = 0; c2 < 8; c2++) {
                ull hv = *reinterpret_cast<const ull*>(hp + 2 * c2);
                fma2(an2, wn2[c2], hv);
            }
            float n0, n1;
            unpack2(n0, n1, an2);
            pn[rr][g][i] = n0 + n1;
        }
        __syncthreads();

        {
            int rr = tid >> 6, ii = tid & 63;
            float o = bn[ii] + pn[rr][0][ii] + pn[rr][1][ii] + pn[rr][2][ii] + pn[rr][3][ii];
            int row = r0 + rr;
            if (row < B) g_obs[row * LODD + ii] = eluf(o) + 1.f;
        }
        __syncthreads();
    }

    red[tid] = lsum;
    __syncthreads();
    #pragma unroll
    for (int s = 128; s > 0; s >>= 1) {
        if (tid < s) red[tid] += red[tid + s];
        __syncthreads();
    }
    if (tid == 0) g_part[blockIdx.x] = red[0];
}

// ---------------------------------------------------------------------------
__global__ void k_sum(int nb) {
    __shared__ float red[256];
    int tid = threadIdx.x;
    float s = 0.f;
    for (int idx = tid; idx < nb; idx += 256) s += g_part[idx];
    red[tid] = s;
    __syncthreads();
    #pragma unroll
    for (int st = 128; st > 0; st >>= 1) {
        if (tid < st) red[tid] += red[tid + st];
        __syncthreads();
    }
    if (tid == 0) g_inv = 1.f / red[0];
}

// ---------------------------------------------------------------------------
// k2: grid = 147 row-blocks x 2 i-halves. 256 threads, launch_bounds(256,2).
// Phase 1 (block-cooperative, brief): logits + softmax -> coeffS[56][16].
// Phase 3 (warp-independent, NO block barriers): warp w owns rows w*7..w*7+6
// of this row-block, lane il owns column i = ihalf + il. Basis slice in smem.
//
// dynamic smem layout (floats):
//   basisS : 0      .. 13824   [mat][d][i_local 32][k pad 18]
//   stW    : 13824  .. 19584   per-warp staging [8][4rows][5arr][36]
//   coeffS : 19584  .. 20480   [56][16]
//   postS  : 20480  .. 20992   [4][128]
//   partcS : 20992  .. 22016   [4][16][16]
//   tcS    : 22016  .. 22144   [128]
// total 22144 floats = 88576 B
// ---------------------------------------------------------------------------
#define K2_SMEM_FLOATS 22144
#define K2_SMEM_BYTES  (K2_SMEM_FLOATS * 4)

__global__ __launch_bounds__(256, 2)
void k2(const float* __restrict__ state,
        const float* __restrict__ Wk, const float* __restrict__ bk,
        const float* __restrict__ ltc, float* __restrict__ out, int B) {
    extern __shared__ float sm[];
    float* basisS = sm;
    float* stW    = sm + 13824;
    float* coeffS = sm + 19584;
    float* postS  = sm + 20480;
    float* partcS = sm + 20992;
    float* tcS    = sm + 22016;

    int tid = threadIdx.x;
    int rowblk = blockIdx.x >> 1;
    int ihalf  = (blockIdx.x & 1) << 5;
    int row_base = rowblk * RPB;

    if (tid < 128) tcS[tid] = eluf(ltc[tid]) + 1.f;

    // fill basis slice for this i-half: 24 chunks of 576 floats (288 ull)
    {
        ull* dst = reinterpret_cast<ull*>(basisS);
        const ull* src = reinterpret_cast<const ull*>(g_tbandP);
        for (int t = tid; t < 24 * 288; t += 256) {
            int md = t / 288, c = t - md * 288;
            dst[md * 288 + c] = src[(md * 64 + ihalf) * 9 + c];
        }
    }

    // ---- Phase 1: logits for 56 rows (block-cooperative) ----
    {
        int klog = tid & 15, seg = tid >> 4;
        float wcf[8];
        {
            const float4* p = reinterpret_cast<const float4*>(Wk + klog * 128 + seg * 8);
            float4 a = p[0], b = p[1];
            wcf[0]=a.x; wcf[1]=a.y; wcf[2]=a.z; wcf[3]=a.w;
            wcf[4]=b.x; wcf[5]=b.y; wcf[6]=b.z; wcf[7]=b.w;
        }
        for (int it = 0; it < 14; it++) {
            int r0 = row_base + it * 4;
            #pragma unroll
            for (int p = 0; p < 2; p++) {
                int idx = tid + p * 256;
                int rr = idx >> 7, c = idx & 127;
                int row = r0 + rr;
                postS[rr * 128 + c] = (row < B) ? state[row * 320 + c] : 0.f;
            }
            __syncthreads();
            #pragma unroll
            for (int rr = 0; rr < 4; rr++) {
                const float* pp = postS + rr * 128 + seg * 8;
                float a = 0.f;
                #pragma unroll
                for (int j = 0; j < 8; j++) a = fmaf(wcf[j], pp[j], a);
                partcS[(rr * 16 + seg) * 16 + klog] = a;
            }
            __syncthreads();
            if (tid < 64) {
                int rr = tid >> 4, k = tid & 15;
                float l = bk[k];
                #pragma unroll
                for (int s = 0; s < 16; s++) l += partcS[(rr * 16 + s) * 16 + k];
                coeffS[(it * 4 + rr) * 16 + k] = l;
            }
            __syncthreads();
        }
        // softmax per row
        if (tid < RPB) {
            float* cr = coeffS + tid * 16;
            float mx = -1e30f;
            #pragma unroll
            for (int k = 0; k < 16; k++) mx = fmaxf(mx, cr[k]);
            float e[16]; float s = 0.f;
            #pragma unroll
            for (int k = 0; k < 16; k++) { e[k] = __expf(cr[k] - mx); s += e[k]; }
            float inv = 1.f / s;
            #pragma unroll
            for (int k = 0; k < 16; k++) cr[k] = e[k] * inv;
        }
    }
    float inv_sum = g_inv;
    __syncthreads();   // last block-wide barrier

    // ---- Phase 3: warp-independent ----
    int w = tid >> 5, il = tid & 31;
    int i = ihalf + il;
    int seg_base = ihalf ? 29 : 0;
    float* stw = stW + w * (4 * 5 * 36);

    for (int grp = 0; grp < 2; grp++) {
        int nr = grp ? 3 : 4;
        int lr0 = w * 7 + grp * 4;
        int r0 = row_base + lr0;

        // stage state segments: nr rows x 5 arrays x 36 cols
        for (int t = il; t < nr * 180; t += 32) {
            int r = t / 180, rem = t - r * 180;
            int arr = rem / 36, c = rem - arr * 36;
            int gr = r0 + r;
            int col = seg_base + c;
            float v = 0.f;
            if (gr < B && col < 64) v = state[gr * 320 + arr * 64 + col];
            stw[t] = v;
        }
        __syncwarp();

        // coeff pairs for 4 rows (pad with last valid row)
        ull cf2[8][4];
        #pragma unroll
        for (int r = 0; r < 4; r++) {
            int lr = lr0 + ((r < nr) ? r : (nr - 1));
            const ull* cp = reinterpret_cast<const ull*>(coeffS + lr * 16);
            #pragma unroll
            for (int kp = 0; kp < 8; kp++) cf2[kp][r] = cp[kp];
        }

        float pmu[4] = {0,0,0,0}, pml[4] = {0,0,0,0};
        float pcu[4] = {0,0,0,0}, pcl[4] = {0,0,0,0}, pcs[4] = {0,0,0,0};

        #pragma unroll
        for (int d = 0; d < 6; d++) {
            float bm_[4][4];   // [mat][row]
            #pragma unroll
            for (int mat = 0; mat < 4; mat++) {
                const ull* bp = reinterpret_cast<const ull*>(
                    basisS + ((mat * 6 + d) * 32 + il) * 18);
                ull bs[8];
                #pragma unroll
                for (int kp = 0; kp < 8; kp++) bs[kp] = bp[kp];
                #pragma unroll
                for (int r = 0; r < 4; r++) {
                    ull acc = 0;
                    #pragma unroll
                    for (int kp = 0; kp < 8; kp++) fma2(acc, bs[kp], cf2[kp][r]);
                    float lo, hi; unpack2(lo, hi, acc);
                    bm_[mat][r] = lo + hi;
                }
            }
            int j = i + d - 3;
            int jc = min(max(j, 0), 63);
            int js = jc - seg_base;
            #pragma unroll
            for (int r = 0; r < 4; r++) {
                const float* sr = stw + r * 180;
                float pu  = sr[js];
                float pl2 = sr[36 + js];
                float cuj = sr[72 + js];
                float clj = sr[108 + js];
                float csj = sr[144 + js];
                float b11 = bm_[0][r], b12 = bm_[1][r], b21 = bm_[2][r], b22 = bm_[3][r];
                pmu[r] = fmaf(b11, pu, pmu[r]); pmu[r] = fmaf(b12, pl2, pmu[r]);
                pml[r] = fmaf(b21, pu, pml[r]); pml[r] = fmaf(b22, pl2, pml[r]);
                pcu[r] = fmaf(b11 * b11, cuj, pcu[r]);
                pcu[r] = fmaf(2.f * b11 * b12, csj, pcu[r]);
                pcu[r] = fmaf(b12 * b12, clj, pcu[r]);
                pcl[r] = fmaf(b21 * b21, cuj, pcl[r]);
                pcl[r] = fmaf(2.f * b21 * b22, csj, pcl[r]);
                pcl[r] = fmaf(b22 * b22, clj, pcl[r]);
                pcs[r] = fmaf(b21 * b11, cuj, pcs[r]);
                pcs[r] = fmaf(b22 * b11 + b21 * b12, csj, pcs[r]);
                pcs[r] = fmaf(b22 * b12, clj, pcs[r]);
            }
        }

        float tcu = tcS[i], tcl2 = tcS[64 + i];
        #pragma unroll
        for (int r = 0; r < 4; r++) {
            if (r >= nr) break;
            int row = r0 + r;
            if (row < B) {
                float pcur = pcu[r] + tcu;
                float pclr = pcl[r] + tcl2;
                float cv = g_c[row * 64 + i];
                float om = g_obs[row * 64 + i];
                float ocov = cv * inv_sum;
                float denom = pcur + ocov;
                float qu = pcur / denom;
                float ql = pcs[r] / denom;
                float res = om - pmu[r];
                float* o = out + row * 320;
                o[i]        = pmu[r] + qu * res;
                o[64 + i]   = pml[r] + ql * res;
                o[128 + i]  = (1.f - qu) * pcur;
                o[192 + i]  = pclr - ql * pcs[r];
                o[256 + i]  = (1.f - qu) * pcs[r];
            }
        }
        __syncwarp();
    }
}

// ---------------------------------------------------------------------------
extern "C" void kernel_launch(void* const* d_in, const int* in_sizes, int n_in,
                              void* d_out, int out_size) {
    const float* input  = (const float*)d_in[0];
    const float* state  = (const float*)d_in[1];
    const float* W_mean = (const float*)d_in[2];
    const float* b_mean = (const float*)d_in[3];
    const float* W_cov  = (const float*)d_in[4];
    const float* b_cov  = (const float*)d_in[5];
    const float* W_norm = (const float*)d_in[6];
    const float* b_norm = (const float*)d_in[7];
    const float* W_coef = (const float*)d_in[8];
    const float* b_coef = (const float*)d_in[9];
    const float* tm11   = (const float*)d_in[10];
    const float* tm12   = (const float*)d_in[11];
    const float* tm21   = (const float*)d_in[12];
    const float* tm22   = (const float*)d_in[13];
    const float* ltc    = (const float*)d_in[14];
    float* out = (float*)d_out;

    int B = in_sizes[0] / ORGD;
    int nb = (B + RPB - 1) / RPB;

    // Unconditional (no static guard — harness forbids call-count behavior).
    // Host-side attribute set; not a stream op, safe under graph capture.
    cudaFuncSetAttribute(k2, cudaFuncAttributeMaxDynamicSharedMemorySize, K2_SMEM_BYTES);

    const int extract_total = 4 * 6 * LODD * 18;
    k_extract<<<(extract_total + 255) / 256, 256>>>(tm11, tm12, tm21, tm22);
    k1<<<nb, 256>>>(input, W_mean, b_mean, W_cov, b_cov, W_norm, b_norm, B);
    k_sum<<<1, 256>>>(nb);
    k2<<<nb * 2, 256, K2_SMEM_BYTES>>>(state, W_coef, b_coef, ltc, out, B);
}